// round 14
// baseline (speedup 1.0000x reference)
#include <cuda_runtime.h>
#include <cuda_fp16.h>
#include <mma.h>
#include <cstdint>

using namespace nvcuda;

namespace {
constexpr int NPTS = 262144;
constexpr int CHN  = 96;
constexpr int KOFF = 27;
constexpr int MT   = 256;        // rows per CTA tile
constexpr int NTHR = 256;        // 8 warps, 32 rows each
constexpr int LDH  = 104;        // padded ld (halfs), 208 B rows
constexpr int QROW = 12;         // 16B chunks per 96-half row
constexpr int A_BYTES = MT * LDH * 2;     // 53248
constexpr int B_BYTES = CHN * LDH * 2;    // 19968
constexpr int SMEM_BYTES = 2 * A_BYTES + 2 * B_BYTES;  // 146432 -> 1 CTA/SM
}

__device__ float  g_dump   [(size_t)NPTS * CHN];     // raw conv accumulators (fp32)
__device__ __half g_hfeats [(size_t)NPTS * CHN];     // feats, fp16
__device__ __half g_scr    [(size_t)NPTS * CHN];     // conv1 activations, fp16
__device__ __half g_wh     [2u * KOFF * CHN * CHN];  // W, fp16

// ---------------------------------------------------------------------------
__device__ __forceinline__ uint32_t smem_u32(const void* p) {
    uint32_t a;
    asm("{ .reg .u64 t; cvta.to.shared.u64 t, %1; cvt.u32.u64 %0, t; }" : "=r"(a) : "l"(p));
    return a;
}
__device__ __forceinline__ void cp_async16(uint32_t dst, const void* src, int src_bytes) {
    asm volatile("cp.async.ca.shared.global [%0], [%1], 16, %2;"
                 :: "r"(dst), "l"(src), "r"(src_bytes) : "memory");
}
__device__ __forceinline__ void cp_commit() {
    asm volatile("cp.async.commit_group;" ::: "memory");
}
__device__ __forceinline__ void cp_wait_all() {
    asm volatile("cp.async.wait_group 0;" ::: "memory");
}

// ---------------------------------------------------------------------------
__global__ void tohalf_kernel(const float2* __restrict__ src, __half2* __restrict__ dst, int n2) {
    for (int i = blockIdx.x * blockDim.x + threadIdx.x; i < n2; i += gridDim.x * blockDim.x)
        dst[i] = __float22half2_rn(src[i]);
}

// ---------------------------------------------------------------------------
// Conv: MT=256 rows/CTA, 8 warps x 32 rows, fp16 m16n16k16.
// Fully double-buffered A and B: all k+1 staging issued BEFORE MMA(k).
// Raw accumulators dumped to gmem (no smem parking).
// ---------------------------------------------------------------------------
__global__ __launch_bounds__(NTHR, 1)
void conv_kernel(const __half* __restrict__ fin,     // fp16 conv input [N,CH]
                 const int*    __restrict__ nidx,    // [K,N]
                 const int*    __restrict__ nmask,   // [K,N]
                 const __half* __restrict__ wh,      // fp16 W [27][CH][CH]
                 float* __restrict__ dump)           // [N,CH] raw accumulators
{
    extern __shared__ char smem[];
    __half* sA[2] = { (__half*)smem, (__half*)(smem + A_BYTES) };
    const uint32_t sAu[2] = { smem_u32(sA[0]), smem_u32(sA[1]) };
    __half* sB[2] = { (__half*)(smem + 2 * A_BYTES),
                      (__half*)(smem + 2 * A_BYTES + B_BYTES) };
    const uint32_t sBu[2] = { smem_u32(sB[0]), smem_u32(sB[1]) };

    const int tid  = threadIdx.x;
    const int warp = tid >> 5;
    const int lane = tid & 31;
    const int row0 = blockIdx.x * MT;

    // each lane owns 1 of its warp's 32 rows
    const int rl    = warp * 32 + lane;
    const int grow  = row0 + rl;
    const uint32_t dstOff = rl * (LDH * 2);

    wmma::fragment<wmma::accumulator, 16, 16, 16, float> acc[12];
#pragma unroll
    for (int i = 0; i < 12; i++) wmma::fill_fragment(acc[i], 0.0f);

    // ---- prologue: stage A(0)+B(0); prefetch idx(1) ----
    {
        const int nb = nidx[grow];
        const int sz = nmask[grow] ? 16 : 0;
        const char* s = (const char*)(fin + (size_t)nb * CHN);
#pragma unroll
        for (int q = 0; q < QROW; q++)
            cp_async16(sAu[0] + dstOff + q * 16, s + q * 16, sz);
        const char* wk = (const char*)wh;
#pragma unroll
        for (int j = 0; j < 5; j++) {
            const int i = tid + j * NTHR;
            if (i < CHN * QROW) {
                const int row = i / QROW, q = i % QROW;
                cp_async16(sBu[0] + row * (LDH * 2) + q * 16, wk + row * (CHN * 2) + q * 16, 16);
            }
        }
        cp_commit();
        cp_wait_all();
        __syncthreads();
    }
    // idx for stage k+1 (loaded one iteration ahead)
    int nbN = nidx[(size_t)1 * NPTS + grow];
    int szN = nmask[(size_t)1 * NPTS + grow] ? 16 : 0;

    for (int k = 0; k < KOFF; k++) {
        const bool more = (k + 1 < KOFF);
        const int cur = k & 1, nxt = cur ^ 1;

        // ---- issue ALL k+1 staging before MMA(k) ----
        if (more) {
            // A(k+1): per-warp self-gather into the other A buffer
            const char* s = (const char*)(fin + (size_t)nbN * CHN);
#pragma unroll
            for (int q = 0; q < QROW; q++)
                cp_async16(sAu[nxt] + dstOff + q * 16, s + q * 16, szN);
            // B(k+1)
            const char* wk = (const char*)(wh + (size_t)(k + 1) * CHN * CHN);
#pragma unroll
            for (int j = 0; j < 5; j++) {
                const int i = tid + j * NTHR;
                if (i < CHN * QROW) {
                    const int row = i / QROW, q = i % QROW;
                    cp_async16(sBu[nxt] + row * (LDH * 2) + q * 16,
                               wk + row * (CHN * 2) + q * 16, 16);
                }
            }
            cp_commit();
            // idx(k+2) prefetch (hidden behind MMA)
            if (k + 2 < KOFF) {
                const size_t o = (size_t)(k + 2) * NPTS;
                nbN = nidx[o + grow];
                szN = nmask[o + grow] ? 16 : 0;
            }
        }

        // ---- MMA(k): warp tile 32 rows x 96 cols ----
        const __half* aBase = sA[cur] + (warp * 32) * LDH;
        const __half* bBase = sB[cur];
#pragma unroll
        for (int kk = 0; kk < CHN / 16; kk++) {
            wmma::fragment<wmma::matrix_a, 16, 16, 16, __half, wmma::row_major> a0, a1;
            wmma::load_matrix_sync(a0, aBase + kk * 16, LDH);
            wmma::load_matrix_sync(a1, aBase + 16 * LDH + kk * 16, LDH);
#pragma unroll
            for (int n = 0; n < 6; n++) {
                wmma::fragment<wmma::matrix_b, 16, 16, 16, __half, wmma::row_major> bf;
                wmma::load_matrix_sync(bf, bBase + (kk * 16) * LDH + n * 16, LDH);
                wmma::mma_sync(acc[n],     a0, bf, acc[n]);
                wmma::mma_sync(acc[6 + n], a1, bf, acc[6 + n]);
            }
        }

        // ---- close iter: k+1 stages have been flying behind the MMA ----
        if (more) {
            cp_wait_all();
            __syncthreads();
        }
    }

    // ---- dump raw accumulators straight to gmem ----
    {
        float* oBase = dump + (size_t)(row0 + warp * 32) * CHN;
#pragma unroll
        for (int n = 0; n < 6; n++) {
            wmma::store_matrix_sync(oBase + n * 16,                 acc[n],     CHN, wmma::mem_row_major);
            wmma::store_matrix_sync(oBase + (size_t)16 * CHN + n * 16, acc[6 + n], CHN, wmma::mem_row_major);
        }
    }
}

// ---------------------------------------------------------------------------
// Epilogue 1: fp32 dump -> bias+PReLU -> fp16 activations
// ---------------------------------------------------------------------------
__global__ void epi1_kernel(const float4* __restrict__ dump,
                            const float* __restrict__ bias,
                            const float* __restrict__ alpha,
                            uint2* __restrict__ outh)
{
    const float av = __ldg(alpha);
    const int n4 = NPTS * CHN / 4;
    for (int i = blockIdx.x * blockDim.x + threadIdx.x; i < n4; i += gridDim.x * blockDim.x) {
        const int q = i % (CHN / 4);
        float4 v  = dump[i];
        float4 bv = reinterpret_cast<const float4*>(bias)[q];
        v.x += bv.x; v.y += bv.y; v.z += bv.z; v.w += bv.w;
        v.x = (v.x > 0.f) ? v.x : av * v.x;
        v.y = (v.y > 0.f) ? v.y : av * v.y;
        v.z = (v.z > 0.f) ? v.z : av * v.z;
        v.w = (v.w > 0.f) ? v.w : av * v.w;
        __half2 h0 = __floats2half2_rn(v.x, v.y);
        __half2 h1 = __floats2half2_rn(v.z, v.w);
        uint2 o;
        o.x = *reinterpret_cast<uint32_t*>(&h0);
        o.y = *reinterpret_cast<uint32_t*>(&h1);
        outh[i] = o;
    }
}

// ---------------------------------------------------------------------------
// Epilogue 2: in-place on d_out: out = PReLU(out + b2 + feats, a2)
// ---------------------------------------------------------------------------
__global__ void epi2_kernel(float4* __restrict__ out,
                            const float4* __restrict__ feats,
                            const float* __restrict__ bias,
                            const float* __restrict__ alpha)
{
    const float av = __ldg(alpha);
    const int n4 = NPTS * CHN / 4;
    for (int i = blockIdx.x * blockDim.x + threadIdx.x; i < n4; i += gridDim.x * blockDim.x) {
        const int q = i % (CHN / 4);
        float4 v  = out[i];
        float4 f  = feats[i];
        float4 bv = reinterpret_cast<const float4*>(bias)[q];
        v.x += bv.x + f.x; v.y += bv.y + f.y; v.z += bv.z + f.z; v.w += bv.w + f.w;
        v.x = (v.x > 0.f) ? v.x : av * v.x;
        v.y = (v.y > 0.f) ? v.y : av * v.y;
        v.z = (v.z > 0.f) ? v.z : av * v.z;
        v.w = (v.w > 0.f) ? v.w : av * v.w;
        out[i] = v;
    }
}

// ---------------------------------------------------------------------------
extern "C" void kernel_launch(void* const* d_in, const int* in_sizes, int n_in,
                              void* d_out, int out_size)
{
    const float* feats = (const float*)d_in[0];
    const int*   nidx  = (const int*)d_in[1];
    const int*   nmask = (const int*)d_in[2];
    const float* W1    = (const float*)d_in[3];
    const float* b1    = (const float*)d_in[4];
    const float* a1    = (const float*)d_in[5];
    const float* W2    = (const float*)d_in[6];
    const float* b2    = (const float*)d_in[7];
    const float* a2    = (const float*)d_in[8];
    float* out = (float*)d_out;

    float  *dump = nullptr;
    __half *hfeats = nullptr, *scr = nullptr, *wh = nullptr;
    cudaGetSymbolAddress((void**)&dump,   g_dump);
    cudaGetSymbolAddress((void**)&hfeats, g_hfeats);
    cudaGetSymbolAddress((void**)&scr,    g_scr);
    cudaGetSymbolAddress((void**)&wh,     g_wh);

    cudaFuncSetAttribute(conv_kernel,
                         cudaFuncAttributeMaxDynamicSharedMemorySize, SMEM_BYTES);

    const int WN2 = KOFF * CHN * CHN / 2;             // 124416
    tohalf_kernel<<<128, 256>>>((const float2*)W1, (__half2*)wh, WN2);
    tohalf_kernel<<<128, 256>>>((const float2*)W2, (__half2*)(wh + (size_t)KOFF * CHN * CHN), WN2);
    tohalf_kernel<<<2048, 256>>>((const float2*)feats, (__half2*)hfeats, NPTS * CHN / 2);

    const int grid = NPTS / MT;  // 1024
    conv_kernel<<<grid, NTHR, SMEM_BYTES>>>(hfeats, nidx, nmask, wh, dump);
    epi1_kernel<<<2048, 256>>>((const float4*)dump, b1, a1, (uint2*)scr);
    conv_kernel<<<grid, NTHR, SMEM_BYTES>>>(scr, nidx, nmask,
                                            wh + (size_t)KOFF * CHN * CHN, out);
    epi2_kernel<<<2048, 256>>>((float4*)out, (const float4*)feats, b2, a2);
}